// round 2
// baseline (speedup 1.0000x reference)
#include <cuda_runtime.h>

#define BB    8
#define NMAX  128
#define HH    192
#define WW    256
#define INV_DOWN 0.125f
#define GRID  (BB * NMAX)

// Scratch + completion counter (graph-replay safe: last block resets counter)
__device__ float2       g_data[GRID];   // {err, valid}
__device__ unsigned int g_count = 0;

// Antiderivative of the bilinear hat kernel, clipped to [-1, 1]
__device__ __forceinline__ float hatP(float u) {
    u = fminf(1.0f, fmaxf(-1.0f, u));
    return (u <= 0.0f) ? 0.5f * (u + 1.0f) * (u + 1.0f)
                       : 0.5f + u - 0.5f * u * u;
}

__global__ __launch_bounds__(128)
void fused_kernel(const float* __restrict__ den,     // [B, 1, H, W]
                  const float* __restrict__ hboxes,  // [B, NMAX, 5]
                  const float* __restrict__ post,    // [B, NMAX, H, W]
                  float* __restrict__ out)
{
    const int bn = blockIdx.x;
    const int b  = bn / NMAX;
    const int t  = threadIdx.x;

    const float* box = hboxes + (size_t)bn * 5;
    const float lab = __ldg(box + 4);
    const float validf = (lab > 0.0f) ? 1.0f : 0.0f;

    float count = 0.0f;

    if (validf > 0.0f) {
        const float x1 = __ldg(box + 0) * INV_DOWN;
        const float y1 = __ldg(box + 1) * INV_DOWN;
        const float x2 = __ldg(box + 2) * INV_DOWN;
        const float y2 = __ldg(box + 3) * INV_DOWN;

        // Hat-weight support: pad 1 cell each side; extras evaluate to 0.
        const int ix0 = max(0, (int)floorf(x1) - 1);
        const int ix1 = min(WW - 1, (int)ceilf(x2) + 1);
        const int iy0 = max(0, (int)floorf(y1) - 1);
        const int iy1 = min(HH - 1, (int)ceilf(y2) + 1);
        const int nx = ix1 - ix0 + 1;   // <= ~24
        const int ny = iy1 - iy0 + 1;   // <= ~24

        __shared__ float wx[32];
        __shared__ float wy[32];
        if (t < nx) {
            float i = (float)(ix0 + t);
            wx[t] = hatP(x2 - i) - hatP(x1 - i);
        }
        if (t < ny) {
            float i = (float)(iy0 + t);
            wy[t] = hatP(y2 - i) - hatP(y1 - i);
        }
        __syncthreads();

        const float* denB  = den  + (size_t)b  * HH * WW;
        const float* postN = post + (size_t)bn * HH * WW;

        const int total = nx * ny;
        float acc = 0.0f;
        for (int k = t; k < total; k += 128) {
            const int jy = k / nx;
            const int jx = k - jy * nx;
            const int idx = (iy0 + jy) * WW + (ix0 + jx);
            acc += wy[jy] * wx[jx] * __ldg(denB + idx) * __ldg(postN + idx);
        }

        #pragma unroll
        for (int o = 16; o > 0; o >>= 1)
            acc += __shfl_down_sync(0xffffffffu, acc, o);

        __shared__ float warpsum[4];
        if ((t & 31) == 0) warpsum[t >> 5] = acc;
        __syncthreads();
        if (t == 0)
            count = warpsum[0] + warpsum[1] + warpsum[2] + warpsum[3];
    }

    // Publish this block's result, then last-arriving block finalizes.
    __shared__ unsigned s_is_last;
    if (t == 0) {
        g_data[bn] = make_float2(fabsf(count - 1.0f) * validf, validf);
        __threadfence();
        unsigned v = atomicAdd(&g_count, 1u);
        s_is_last = (v == (unsigned)(GRID - 1)) ? 1u : 0u;
    }
    __syncthreads();

    if (s_is_last) {
        // 128 threads: 16 threads per image, each sums 8 entries.
        const int img = t >> 4;       // 0..7
        const int sub = t & 15;
        float e = 0.0f, v = 0.0f;
        #pragma unroll
        for (int k = 0; k < NMAX / 16; k++) {
            float2 d = __ldcg(&g_data[img * NMAX + sub + k * 16]);
            e += d.x;
            v += d.y;
        }
        #pragma unroll
        for (int o = 8; o > 0; o >>= 1) {
            e += __shfl_down_sync(0xffffffffu, e, o, 16);
            v += __shfl_down_sync(0xffffffffu, v, o, 16);
        }
        __shared__ float s_img[BB];
        if (sub == 0)
            s_img[img] = (v > 0.0f) ? (e / fmaxf(v, 1.0f)) : 0.0f;
        __syncthreads();
        if (t == 0) {
            float tot = 0.0f;
            #pragma unroll
            for (int i = 0; i < BB; i++) tot += s_img[i];
            out[0] = tot;
            g_count = 0;   // reset for next graph replay
        }
    }
}

extern "C" void kernel_launch(void* const* d_in, const int* in_sizes, int n_in,
                              void* d_out, int out_size)
{
    // metadata order: cls(0), reg(1), off(2), den(3), fboxes(4), hboxes(5),
    //                 ctr_masks(6), post_probs(7)
    const float* den    = (const float*)d_in[3];
    const float* hboxes = (const float*)d_in[5];
    const float* post   = (const float*)d_in[7];
    float* out = (float*)d_out;

    fused_kernel<<<GRID, 128>>>(den, hboxes, post, out);
}